// round 5
// baseline (speedup 1.0000x reference)
#include <cuda_runtime.h>

// SpatialTransformer: affine grid + bilinear sampling.
// Corner-register reuse along oy + software pipelining: next row's loads are
// issued before the current row's blend, so each load has a full iteration of
// independent work (plus warp interleaving) to cover L2/DRAM latency.
// image: [B=16, H=256, W=256, C=64] fp32, theta: [B=16, 6], out same shape.

constexpr int B_  = 16;
constexpr int H_  = 256;
constexpr int W_  = 256;
constexpr int C_  = 64;
constexpr int OH_ = 256;
constexpr int OW_ = 256;
constexpr int K_  = 16;   // oy pixels per thread (OH_/K_ = 16 strips)

__global__ __launch_bounds__(256) void stn_kernel(
    const float* __restrict__ img,
    const float* __restrict__ theta,
    float* __restrict__ out)
{
    const int gid = blockIdx.x * blockDim.x + threadIdx.x;
    const int c4  = gid & 15;          // float4 chunk (4 channels)
    const int t   = gid >> 4;          // pixel-column index
    const int ox  = t & (OW_ - 1);
    const int t2  = t >> 8;
    const int oyb = (t2 & (OH_ / K_ - 1)) * K_;
    const int b   = t2 >> 4;           // OH_/K_ = 16 -> shift 4

    const float th0 = __ldg(theta + b * 6 + 0);
    const float th1 = __ldg(theta + b * 6 + 1);
    const float th2 = __ldg(theta + b * 6 + 2);
    const float th3 = __ldg(theta + b * 6 + 3);
    const float th4 = __ldg(theta + b * 6 + 4);
    const float th5 = __ldg(theta + b * 6 + 5);

    // xt = th1*ys + (th0*xs + th2),  yt = th4*ys + (th3*xs + th5)
    const float xs = fmaf((float)ox, 2.0f / (OW_ - 1), -1.0f);
    const float xc = fmaf(th0, xs, th2);
    const float yc = fmaf(th3, xs, th5);

    const float4* __restrict__ img4 = (const float4*)img + c4;
    float4* __restrict__ out4 =
        (float4*)out + (((b * OH_ + oyb) * OW_ + ox) * (C_ / 4) + c4);

    const int rowb = b * H_;

    // ---- prologue: full 4-corner load for row oyb ----
    float x, y;
    int ix0, ix1, iy0, iy1;
    {
        const float ys = fmaf((float)oyb, 2.0f / (OH_ - 1), -1.0f);
        x = (fmaf(th1, ys, xc) + 1.0f) * (0.5f * (float)W_);
        y = (fmaf(th4, ys, yc) + 1.0f) * (0.5f * (float)H_);
        const float xf = floorf(x), yf = floorf(y);
        ix0 = min(max((int)xf,     0), W_ - 1);
        ix1 = min(max((int)xf + 1, 0), W_ - 1);
        iy0 = min(max((int)yf,     0), H_ - 1);
        iy1 = min(max((int)yf + 1, 0), H_ - 1);
    }
    float4 Ia = __ldg(img4 + ((rowb + iy0) * W_ + ix0) * (C_ / 4));
    float4 Ib = __ldg(img4 + ((rowb + iy1) * W_ + ix0) * (C_ / 4));
    float4 Ic = __ldg(img4 + ((rowb + iy0) * W_ + ix1) * (C_ / 4));
    float4 Id = __ldg(img4 + ((rowb + iy1) * W_ + ix1) * (C_ / 4));

#pragma unroll
    for (int k = 0; k < K_; k++) {
        // ---- prefetch row k+1: compute indices, issue loads BEFORE blending k ----
        float nx = 0.f, ny = 0.f;
        int nix0 = 0, nix1 = 0, niy0 = 0, niy1 = 0;
        float4 nIa, nIb, nIc, nId;
        nIa = nIb = nIc = nId = make_float4(0.f, 0.f, 0.f, 0.f);
        if (k + 1 < K_) {
            const float ys = fmaf((float)(oyb + k + 1), 2.0f / (OH_ - 1), -1.0f);
            nx = (fmaf(th1, ys, xc) + 1.0f) * (0.5f * (float)W_);
            ny = (fmaf(th4, ys, yc) + 1.0f) * (0.5f * (float)H_);
            const float xf = floorf(nx), yf = floorf(ny);
            nix0 = min(max((int)xf,     0), W_ - 1);
            nix1 = min(max((int)xf + 1, 0), W_ - 1);
            niy0 = min(max((int)yf,     0), H_ - 1);
            niy1 = min(max((int)yf + 1, 0), H_ - 1);

            const bool samex = (nix0 == ix0) && (nix1 == ix1);
            if (samex && niy0 == iy0 && niy1 == iy1) {
                nIa = Ia; nIb = Ib; nIc = Ic; nId = Id;   // zero loads
            } else if (samex && niy0 == iy1) {
                nIa = Ib; nIc = Id;                        // register shift
                nIb = __ldg(img4 + ((rowb + niy1) * W_ + nix0) * (C_ / 4));
                nId = __ldg(img4 + ((rowb + niy1) * W_ + nix1) * (C_ / 4));
            } else {
                nIa = __ldg(img4 + ((rowb + niy0) * W_ + nix0) * (C_ / 4));
                nIb = __ldg(img4 + ((rowb + niy1) * W_ + nix0) * (C_ / 4));
                nIc = __ldg(img4 + ((rowb + niy0) * W_ + nix1) * (C_ / 4));
                nId = __ldg(img4 + ((rowb + niy1) * W_ + nix1) * (C_ / 4));
            }
        }

        // ---- blend + store row k (weights from CLIPPED corners, as reference) ----
        const float x0f = (float)ix0, x1f = (float)ix1;
        const float y0f = (float)iy0, y1f = (float)iy1;
        const float wa = (x1f - x) * (y1f - y);
        const float wb = (x1f - x) * (y - y0f);
        const float wc = (x - x0f) * (y1f - y);
        const float wd = (x - x0f) * (y - y0f);

        float4 o;
        o.x = fmaf(wa, Ia.x, fmaf(wb, Ib.x, fmaf(wc, Ic.x, wd * Id.x)));
        o.y = fmaf(wa, Ia.y, fmaf(wb, Ib.y, fmaf(wc, Ic.y, wd * Id.y)));
        o.z = fmaf(wa, Ia.z, fmaf(wb, Ib.z, fmaf(wc, Ic.z, wd * Id.z)));
        o.w = fmaf(wa, Ia.w, fmaf(wb, Ib.w, fmaf(wc, Ic.w, wd * Id.w)));

        *out4 = o;
        out4 += OW_ * (C_ / 4);

        // ---- rotate pipeline state ----
        if (k + 1 < K_) {
            Ia = nIa; Ib = nIb; Ic = nIc; Id = nId;
            x = nx; y = ny;
            ix0 = nix0; ix1 = nix1; iy0 = niy0; iy1 = niy1;
        }
    }
}

extern "C" void kernel_launch(void* const* d_in, const int* in_sizes, int n_in,
                              void* d_out, int out_size)
{
    const float* img   = (const float*)d_in[0];
    const float* theta = (const float*)d_in[1];
    float* out = (float*)d_out;

    // threads = B*OW*(OH/K)*16 = 16*256*16*16 = 1,048,576 -> 4096 blocks
    const int threads = 256;
    const int blocks  = (B_ * OW_ * (OH_ / K_) * 16) / threads;

    stn_kernel<<<blocks, threads>>>(img, theta, out);
}

// round 8
// speedup vs baseline: 1.1957x; 1.1957x over previous
#include <cuda_runtime.h>

// SpatialTransformer: affine grid + bilinear sampling.
// oy-walk with branch-free bottom-row loads: the two iy1-row corner loads are
// unconditional straight-line code (batchable across the unrolled loop -> high
// MLP); only top-row corners conditionally reuse the previous bottom pair.
// image: [B=16, H=256, W=256, C=64] fp32, theta: [B=16, 6], out same shape.

constexpr int B_  = 16;
constexpr int H_  = 256;
constexpr int W_  = 256;
constexpr int C_  = 64;
constexpr int OH_ = 256;
constexpr int OW_ = 256;
constexpr int K_  = 8;   // oy pixels per thread (OH_/K_ = 32 strips)

__global__ __launch_bounds__(256) void stn_kernel(
    const float* __restrict__ img,
    const float* __restrict__ theta,
    float* __restrict__ out)
{
    const int gid = blockIdx.x * blockDim.x + threadIdx.x;
    const int c4  = gid & 15;          // float4 chunk (4 channels)
    const int t   = gid >> 4;          // pixel-column index
    const int ox  = t & (OW_ - 1);
    const int t2  = t >> 8;
    const int oyb = (t2 & (OH_ / K_ - 1)) * K_;
    const int b   = t2 >> 5;           // OH_/K_ = 32 -> shift 5

    const float th0 = __ldg(theta + b * 6 + 0);
    const float th1 = __ldg(theta + b * 6 + 1);
    const float th2 = __ldg(theta + b * 6 + 2);
    const float th3 = __ldg(theta + b * 6 + 3);
    const float th4 = __ldg(theta + b * 6 + 4);
    const float th5 = __ldg(theta + b * 6 + 5);

    // xt = th1*ys + (th0*xs + th2),  yt = th4*ys + (th3*xs + th5)
    const float xs = fmaf((float)ox, 2.0f / (OW_ - 1), -1.0f);
    const float xc = fmaf(th0, xs, th2);
    const float yc = fmaf(th3, xs, th5);

    const float4* __restrict__ img4 = (const float4*)img + c4;
    float4* __restrict__ out4 =
        (float4*)out + (((b * OH_ + oyb) * OW_ + ox) * (C_ / 4) + c4);

    const int rowb = b * H_;

    // carried state: previous bottom-row corner values + indices
    float4 Pb, Pd;
    Pb = Pd = make_float4(0.f, 0.f, 0.f, 0.f);
    int px0 = -0x40000000, px1 = -0x40000000, py1 = -0x40000000;

#pragma unroll
    for (int k = 0; k < K_; k++) {
        const float ys = fmaf((float)(oyb + k), 2.0f / (OH_ - 1), -1.0f);
        const float x  = (fmaf(th1, ys, xc) + 1.0f) * (0.5f * (float)W_);
        const float y  = (fmaf(th4, ys, yc) + 1.0f) * (0.5f * (float)H_);

        const float xf = floorf(x), yf = floorf(y);
        const int ix0 = min(max((int)xf,     0), W_ - 1);
        const int ix1 = min(max((int)xf + 1, 0), W_ - 1);
        const int iy0 = min(max((int)yf,     0), H_ - 1);
        const int iy1 = min(max((int)yf + 1, 0), H_ - 1);

        // ---- unconditional bottom-row loads: always correct, branch-free ----
        const float4 Nb = __ldg(img4 + ((rowb + iy1) * W_ + ix0) * (C_ / 4));
        const float4 Nd = __ldg(img4 + ((rowb + iy1) * W_ + ix1) * (C_ / 4));

        // ---- top-row corners: reuse previous bottom pair when row shifted +1 ----
        float4 Na, Nc;
        const bool ru = (ix0 == px0) && (ix1 == px1) && (iy0 == py1);
        if (ru) {
            Na = Pb;
            Nc = Pd;
        } else {
            // rare path (~10% + prologue); address usually touched recently -> L1 hit
            Na = __ldg(img4 + ((rowb + iy0) * W_ + ix0) * (C_ / 4));
            Nc = __ldg(img4 + ((rowb + iy0) * W_ + ix1) * (C_ / 4));
        }

        // weights from CLIPPED corners cast back to float (matches reference)
        const float x0f = (float)ix0, x1f = (float)ix1;
        const float y0f = (float)iy0, y1f = (float)iy1;
        const float wa = (x1f - x) * (y1f - y);
        const float wb = (x1f - x) * (y - y0f);
        const float wc = (x - x0f) * (y1f - y);
        const float wd = (x - x0f) * (y - y0f);

        float4 o;
        o.x = fmaf(wa, Na.x, fmaf(wb, Nb.x, fmaf(wc, Nc.x, wd * Nd.x)));
        o.y = fmaf(wa, Na.y, fmaf(wb, Nb.y, fmaf(wc, Nc.y, wd * Nd.y)));
        o.z = fmaf(wa, Na.z, fmaf(wb, Nb.z, fmaf(wc, Nc.z, wd * Nd.z)));
        o.w = fmaf(wa, Na.w, fmaf(wb, Nb.w, fmaf(wc, Nc.w, wd * Nd.w)));

        *out4 = o;
        out4 += OW_ * (C_ / 4);

        Pb = Nb; Pd = Nd;
        px0 = ix0; px1 = ix1; py1 = iy1;
    }
}

extern "C" void kernel_launch(void* const* d_in, const int* in_sizes, int n_in,
                              void* d_out, int out_size)
{
    const float* img   = (const float*)d_in[0];
    const float* theta = (const float*)d_in[1];
    float* out = (float*)d_out;

    // threads = B*OW*(OH/K)*16 = 16*256*32*16 = 2,097,152 -> 8192 blocks
    const int threads = 256;
    const int blocks  = (B_ * OW_ * (OH_ / K_) * 16) / threads;

    stn_kernel<<<blocks, threads>>>(img, theta, out);
}